// round 2
// baseline (speedup 1.0000x reference)
#include <cuda_runtime.h>

// MySoftBCELoss: B=1048576 rows, C=32 classes, fp32 in, scalar fp32 out.
//   pred = clamp(sigmoid(logits), 1e-7, 1-1e-7)
//   label = argmax(target, axis=1)
//   loss0 = mean_c(t*log p + (1-t)*log(1-p))            (label == 0)
//   loss1 = t[lab]*log p[lab] + log(1-p[:,0])           (label != 0)
//   out   = -mean(where(label==0, loss0, loss1))
//
// Layout: 8 threads per row, each owns 4 classes via one float4 per input.
// Math:  s = log1p(exp(-|x|));  log p = min(x,0)-s;  log(1-p) = -max(x,0)-s
//        clamp applied in log-domain (log is monotone).

static constexpr int   BROWS   = 1048576;
static constexpr float LOG_EPS = -16.118095651f;    // logf(1e-7f)
static constexpr float LOG_1ME = -1.00000005e-7f;   // logf(1.0f - 1e-7f)

__device__ double g_acc;

__global__ void k_init() { g_acc = 0.0; }

__global__ void __launch_bounds__(256)
k_main(const float* __restrict__ logits, const float* __restrict__ target) {
    const int lane     = threadIdx.x & 31;
    const int nthreads = gridDim.x * blockDim.x;      // multiple of 32
    const int ntasks   = BROWS * 8;                   // 8 tasks (threads) per row

    float tacc = 0.0f;   // leader-lane accumulator of per-row losses

    for (int task = blockIdx.x * blockDim.x + threadIdx.x; task < ntasks;
         task += nthreads) {
        // task == row*8 + sub ; float4 index into [B,32] fp32 is exactly `task`
        const float4 lg = __ldg(reinterpret_cast<const float4*>(logits) + task);
        const float4 tg = __ldg(reinterpret_cast<const float4*>(target) + task);
        const int sub = task & 7;

        const float xv[4] = {lg.x, lg.y, lg.z, lg.w};
        const float tv[4] = {tg.x, tg.y, tg.z, tg.w};

        float s = 0.0f;                // partial soft-BCE sum over my 4 classes
        float maxv = -1.0f;            // targets are uniform[0,1) -> -1 is safe floor
        int   maxi = 1 << 30;
        float maxlp = 0.0f;
        float l1p0 = 0.0f;             // log(1-p) of class 0 (valid on sub==0)

        #pragma unroll
        for (int j = 0; j < 4; ++j) {
            const float x = xv[j], t = tv[j];
            const float sp  = __logf(1.0f + __expf(-fabsf(x)));   // log1p(e^-|x|)
            float lp  = fminf(x, 0.0f) - sp;                      // log p
            float l1p = -fmaxf(x, 0.0f) - sp;                     // log(1-p)
            lp  = fminf(fmaxf(lp,  LOG_EPS), LOG_1ME);            // clamp in log-domain
            l1p = fminf(fmaxf(l1p, LOG_EPS), LOG_1ME);
            s += t * lp + (1.0f - t) * l1p;
            const int idx = sub * 4 + j;
            if (t > maxv) { maxv = t; maxi = idx; maxlp = lp; }   // first-max kept
            if (idx == 0) l1p0 = l1p;
        }

        // Reduce across the 8 lanes of this row (xor offsets 1,2,4 stay in-group).
        #pragma unroll
        for (int o = 1; o < 8; o <<= 1) {
            s += __shfl_xor_sync(0xffffffffu, s, o);
            const float ov  = __shfl_xor_sync(0xffffffffu, maxv,  o);
            const int   oi  = __shfl_xor_sync(0xffffffffu, maxi,  o);
            const float olp = __shfl_xor_sync(0xffffffffu, maxlp, o);
            if (ov > maxv || (ov == maxv && oi < maxi)) {
                maxv = ov; maxi = oi; maxlp = olp;
            }
        }
        // Broadcast class-0 log(1-p) from the group's sub==0 lane.
        l1p0 = __shfl_sync(0xffffffffu, l1p0, lane & ~7);

        if ((lane & 7) == 0) {
            const float pr = (maxi == 0) ? (s * (1.0f / 32.0f))
                                         : fmaf(maxv, maxlp, l1p0);  // NEG_WEIGHT=1
            tacc += pr;
        }
    }

    // Warp reduction (only lanes 0,8,16,24 hold nonzero).
    #pragma unroll
    for (int o = 1; o < 32; o <<= 1)
        tacc += __shfl_xor_sync(0xffffffffu, tacc, o);

    __shared__ float wsum[8];
    if (lane == 0) wsum[threadIdx.x >> 5] = tacc;
    __syncthreads();
    if (threadIdx.x == 0) {
        float b = 0.0f;
        #pragma unroll
        for (int i = 0; i < 8; ++i) b += wsum[i];
        atomicAdd(&g_acc, (double)b);   // ~2368 single-address atomics total
    }
}

__global__ void k_fin(float* out) {
    out[0] = (float)(-g_acc / (double)BROWS);
}

extern "C" void kernel_launch(void* const* d_in, const int* in_sizes, int n_in,
                              void* d_out, int out_size) {
    const float* logits = (const float*)d_in[0];
    const float* target = (const float*)d_in[1];
    float* out = (float*)d_out;

    k_init<<<1, 1>>>();
    k_main<<<2368, 256>>>(logits, target);   // 148 SMs * 16 CTAs
    k_fin<<<1, 1>>>(out);
}

// round 3
// speedup vs baseline: 1.2462x; 1.2462x over previous
#include <cuda_runtime.h>

// MySoftBCELoss: B=1048576 rows, C=32 classes, fp32 in, scalar fp32 out.
//   pred = clamp(sigmoid(logits), 1e-7, 1-1e-7)
//   label = argmax(target, axis=1)      (first max wins)
//   loss0 = mean_c(t*log p + (1-t)*log(1-p))            (label == 0)
//   loss1 = t[lab]*log p[lab] + log(1-p[:,0])           (label != 0)
//   out   = -mean(per_row)
//
// Single fused kernel: 4 threads per row (2 float4 per array each),
// packed-key argmax reduction over 2 shuffle stages, per-block partial
// into __device__ array, last-block finalize (self-resetting counter).

static constexpr int   BROWS   = 1048576;
static constexpr float LOG_EPS = -16.118095651f;    // logf(1e-7f)
static constexpr float LOG_1ME = -1.00000005e-7f;   // logf(1.0f - 1e-7f)

static constexpr int NBLK = 2048;
static constexpr int NTHR = 256;
static constexpr int NITER = (BROWS * 4) / (NBLK * NTHR);   // 8, exact

__device__ double       g_part[NBLK];
__device__ unsigned int g_count = 0;   // self-resets each launch -> graph-safe

__global__ void __launch_bounds__(NTHR)
k_fused(const float* __restrict__ logits, const float* __restrict__ target,
        float* __restrict__ out) {
    const int tid  = blockIdx.x * NTHR + threadIdx.x;
    const int lane = threadIdx.x & 31;
    const int sub  = lane & 3;          // position within 4-lane row group

    float tacc = 0.0f;                  // per-thread sum of per-row losses

    #pragma unroll 4
    for (int it = 0; it < NITER; ++it) {
        const int  task = it * (NBLK * NTHR) + tid;          // row*4 + sub
        const long f4   = (long)task * 2;                    // = row*8 + sub*2

        // 4 independent 16B loads, streaming (no reuse, > L2 capacity)
        const float4 lg0 = __ldcs(reinterpret_cast<const float4*>(logits) + f4);
        const float4 lg1 = __ldcs(reinterpret_cast<const float4*>(logits) + f4 + 1);
        const float4 tg0 = __ldcs(reinterpret_cast<const float4*>(target) + f4);
        const float4 tg1 = __ldcs(reinterpret_cast<const float4*>(target) + f4 + 1);

        const float xv[8] = {lg0.x, lg0.y, lg0.z, lg0.w, lg1.x, lg1.y, lg1.z, lg1.w};
        const float tv[8] = {tg0.x, tg0.y, tg0.z, tg0.w, tg1.x, tg1.y, tg1.z, tg1.w};

        float s = 0.0f;            // partial soft-BCE sum over my 8 classes
        float maxv = -1.0f;        // targets are uniform [0,1)
        int   maxi = 0;
        float maxlp = 0.0f;
        float l1p0  = 0.0f;        // log(1-p) of class 0 (valid on sub==0)

        #pragma unroll
        for (int e = 0; e < 8; ++e) {
            const float x = xv[e], t = tv[e];
            const float sp  = __logf(1.0f + __expf(-fabsf(x)));   // log1p(e^-|x|)
            float lp  = fminf(x, 0.0f) - sp;                      // log p
            float l1p = -fmaxf(x, 0.0f) - sp;                     // log(1-p)
            lp  = fminf(fmaxf(lp,  LOG_EPS), LOG_1ME);            // clamp (log-domain)
            l1p = fminf(fmaxf(l1p, LOG_EPS), LOG_1ME);
            s += t * lp + (1.0f - t) * l1p;
            if (t > maxv) { maxv = t; maxi = sub * 8 + e; maxlp = lp; }
            if (e == 0 && sub == 0) l1p0 = l1p;
        }

        // Packed argmax key: value bits (positive float => monotone in uint),
        // low 6 bits encode first-max tie-break (smaller idx wins on equal value).
        unsigned long long key =
            ((unsigned long long)__float_as_uint(maxv) << 6) |
            (unsigned)(63 - maxi);

        // 2-stage reduction across the 4-lane group (xor 1,2 stay in-group).
        #pragma unroll
        for (int o = 1; o < 4; o <<= 1) {
            s += __shfl_xor_sync(0xffffffffu, s, o);
            const unsigned long long ok = __shfl_xor_sync(0xffffffffu, key, o);
            key = (ok > key) ? ok : key;
        }
        maxi = 63 - (int)(key & 63u);
        const float g_maxv = __uint_as_float((unsigned)(key >> 6));

        // Fetch log p at the winning class from the winning lane,
        // and class-0 log(1-p) from the group's sub==0 lane.
        const float g_maxlp = __shfl_sync(0xffffffffu, maxlp,
                                          (lane & ~3) + (maxi >> 3));
        const float g_l1p0  = __shfl_sync(0xffffffffu, l1p0, lane & ~3);

        if (sub == 0) {
            tacc += (maxi == 0) ? (s * (1.0f / 32.0f))
                                : fmaf(g_maxv, g_maxlp, g_l1p0);  // NEG_WEIGHT=1
        }
    }

    // Block reduction (lanes with sub!=0 hold 0, just sum everything).
    #pragma unroll
    for (int o = 1; o < 32; o <<= 1)
        tacc += __shfl_xor_sync(0xffffffffu, tacc, o);

    __shared__ float wsum[NTHR / 32];
    if (lane == 0) wsum[threadIdx.x >> 5] = tacc;
    __syncthreads();

    __shared__ bool is_last;
    if (threadIdx.x == 0) {
        float b = 0.0f;
        #pragma unroll
        for (int i = 0; i < NTHR / 32; ++i) b += wsum[i];
        g_part[blockIdx.x] = (double)b;
        __threadfence();
        const unsigned prev = atomicAdd(&g_count, 1u);
        is_last = (prev == (unsigned)(NBLK - 1));
    }
    __syncthreads();

    // Last block to finish sums the partials and writes the scalar.
    if (is_last) {
        double v = 0.0;
        for (int i = threadIdx.x; i < NBLK; i += NTHR) v += g_part[i];
        #pragma unroll
        for (int o = 1; o < 32; o <<= 1)
            v += __shfl_xor_sync(0xffffffffu, v, o);
        __shared__ double dsum[NTHR / 32];
        if (lane == 0) dsum[threadIdx.x >> 5] = v;
        __syncthreads();
        if (threadIdx.x == 0) {
            double tot = 0.0;
            #pragma unroll
            for (int i = 0; i < NTHR / 32; ++i) tot += dsum[i];
            out[0] = (float)(-tot / (double)BROWS);
            g_count = 0;               // reset for next (graph-replayed) launch
        }
    }
}

extern "C" void kernel_launch(void* const* d_in, const int* in_sizes, int n_in,
                              void* d_out, int out_size) {
    const float* logits = (const float*)d_in[0];
    const float* target = (const float*)d_in[1];
    k_fused<<<NBLK, NTHR>>>(logits, target, (float*)d_out);
}